// round 11
// baseline (speedup 1.0000x reference)
#include <cuda_runtime.h>
#include <cuda_bf16.h>

// Output: out[b,c,h,w] = x[b,c, 2h+o, 2w+p], where (o,p)=divmod(i,2).
// B*C = 24 images, in 2048x2048, out 1024x1024.
// Best-of-session structure (R7): each thread does TWO 256-bit loads
// covering 64B of the source row, lane-selects by p, and ONE 256-bit
// streaming store (st.global.cs.v8.f32) writing 32B of output.
// Delta vs R7: loads carry the L2::256B fetch-granularity hint — source
// rows are 8KB-aligned fully-consumed streams, so 256B DRAM bursts halve
// read-command count with zero over-fetch.

static constexpr int H_IN  = 2048;
static constexpr int W_IN  = 2048;
static constexpr int H_OUT = 1024;
static constexpr int W_OUT = 1024;
static constexpr int W_OUT8 = W_OUT / 8;              // 128 v8-groups per out row
static constexpr long IMG_IN  = (long)H_IN * W_IN;    // 4,194,304 floats

__global__ void __launch_bounds__(256) slice_stride2_kernel(
    const float* __restrict__ x,
    const int* __restrict__ ip,
    float* __restrict__ out,
    long total8)
{
    long t = (long)blockIdx.x * blockDim.x + threadIdx.x;
    if (t >= total8) return;

    const int iv = ip[0];
    const int o = (iv >> 1) & 1;
    const int p = iv & 1;

    // t -> (img, out_row, out_group8). W_OUT8=128 (7 bits), H_OUT=1024 (10 bits).
    const int  g8  = (int)(t & (W_OUT8 - 1));
    const int  row = (int)((t >> 7) & (H_OUT - 1));
    const long img = t >> 17;

    const float* src = x + img * IMG_IN
                         + (long)(2 * row + o) * W_IN + (long)g8 * 16;

    // Two independent 256-bit loads with 256B L2 fetch granularity.
    float a0, a1, a2, a3, a4, a5, a6, a7;
    float b0, b1, b2, b3, b4, b5, b6, b7;
    asm volatile(
        "ld.global.nc.L2::256B.v8.f32 {%0, %1, %2, %3, %4, %5, %6, %7}, [%8];"
        : "=f"(a0), "=f"(a1), "=f"(a2), "=f"(a3),
          "=f"(a4), "=f"(a5), "=f"(a6), "=f"(a7)
        : "l"(src));
    asm volatile(
        "ld.global.nc.L2::256B.v8.f32 {%0, %1, %2, %3, %4, %5, %6, %7}, [%8];"
        : "=f"(b0), "=f"(b1), "=f"(b2), "=f"(b3),
          "=f"(b4), "=f"(b5), "=f"(b6), "=f"(b7)
        : "l"(src + 8));

    float r0, r1, r2, r3, r4, r5, r6, r7;
    if (p == 0) {
        r0 = a0; r1 = a2; r2 = a4; r3 = a6;
        r4 = b0; r5 = b2; r6 = b4; r7 = b6;
    } else {
        r0 = a1; r1 = a3; r2 = a5; r3 = a7;
        r4 = b1; r5 = b3; r6 = b5; r7 = b7;
    }

    // One 256-bit streaming store: 8 consecutive output floats (32B aligned).
    float* dst = out + t * 8;
    asm volatile(
        "st.global.cs.v8.f32 [%0], {%1, %2, %3, %4, %5, %6, %7, %8};"
        :: "l"(dst),
           "f"(r0), "f"(r1), "f"(r2), "f"(r3),
           "f"(r4), "f"(r5), "f"(r6), "f"(r7)
        : "memory");
}

extern "C" void kernel_launch(void* const* d_in, const int* in_sizes, int n_in,
                              void* d_out, int out_size)
{
    const float* x  = (const float*)d_in[0];
    const int*   ip = (const int*)d_in[1];
    float* out = (float*)d_out;

    const long total8 = (long)out_size / 8;   // 3,145,728
    const int threads = 256;
    const int blocks = (int)((total8 + threads - 1) / threads);  // 12288
    slice_stride2_kernel<<<blocks, threads>>>(x, ip, out, total8);
}

// round 12
// speedup vs baseline: 1.0185x; 1.0185x over previous
#include <cuda_runtime.h>
#include <cuda_bf16.h>

// Output: out[b,c,h,w] = x[b,c, 2h+o, 2w+p], where (o,p)=divmod(i,2).
// B*C = 24 images, in 2048x2048, out 1024x1024.
// FINAL (best of session, measured twice at 41.6-41.7us, DRAM ~79%,
// ~7.0 TB/s effective): each thread does TWO 256-bit loads
// (ld.global.nc.v8.f32) covering 64B of the source row, lane-selects by p,
// and ONE 256-bit streaming store (st.global.cs.v8.f32) writing 32B of
// output. Warp-level: two coalesced 1024B read requests + one coalesced
// 1024B write request. Loads keep default L2 policy (cross-replay read
// hits observed in ncu; .cs and L2::256B variants both measured worse);
// the store is evict-first so the write stream doesn't displace read lines.
// Deeper per-thread MLP (4 loads), persistent grids, and 128-bit variants
// all measured equal or worse — this shape is the converged optimum.

static constexpr int H_IN  = 2048;
static constexpr int W_IN  = 2048;
static constexpr int H_OUT = 1024;
static constexpr int W_OUT = 1024;
static constexpr int W_OUT8 = W_OUT / 8;              // 128 v8-groups per out row
static constexpr long IMG_IN  = (long)H_IN * W_IN;    // 4,194,304 floats

__global__ void __launch_bounds__(256) slice_stride2_kernel(
    const float* __restrict__ x,
    const int* __restrict__ ip,
    float* __restrict__ out,
    long total8)
{
    long t = (long)blockIdx.x * blockDim.x + threadIdx.x;
    if (t >= total8) return;

    const int iv = ip[0];
    const int o = (iv >> 1) & 1;
    const int p = iv & 1;

    // t -> (img, out_row, out_group8). W_OUT8=128 (7 bits), H_OUT=1024 (10 bits).
    const int  g8  = (int)(t & (W_OUT8 - 1));
    const int  row = (int)((t >> 7) & (H_OUT - 1));
    const long img = t >> 17;

    const float* src = x + img * IMG_IN
                         + (long)(2 * row + o) * W_IN + (long)g8 * 16;

    // Two independent 256-bit loads: 16 consecutive source floats.
    float a0, a1, a2, a3, a4, a5, a6, a7;
    float b0, b1, b2, b3, b4, b5, b6, b7;
    asm volatile(
        "ld.global.nc.v8.f32 {%0, %1, %2, %3, %4, %5, %6, %7}, [%8];"
        : "=f"(a0), "=f"(a1), "=f"(a2), "=f"(a3),
          "=f"(a4), "=f"(a5), "=f"(a6), "=f"(a7)
        : "l"(src));
    asm volatile(
        "ld.global.nc.v8.f32 {%0, %1, %2, %3, %4, %5, %6, %7}, [%8];"
        : "=f"(b0), "=f"(b1), "=f"(b2), "=f"(b3),
          "=f"(b4), "=f"(b5), "=f"(b6), "=f"(b7)
        : "l"(src + 8));

    float r0, r1, r2, r3, r4, r5, r6, r7;
    if (p == 0) {
        r0 = a0; r1 = a2; r2 = a4; r3 = a6;
        r4 = b0; r5 = b2; r6 = b4; r7 = b6;
    } else {
        r0 = a1; r1 = a3; r2 = a5; r3 = a7;
        r4 = b1; r5 = b3; r6 = b5; r7 = b7;
    }

    // One 256-bit streaming store: 8 consecutive output floats (32B aligned).
    float* dst = out + t * 8;
    asm volatile(
        "st.global.cs.v8.f32 [%0], {%1, %2, %3, %4, %5, %6, %7, %8};"
        :: "l"(dst),
           "f"(r0), "f"(r1), "f"(r2), "f"(r3),
           "f"(r4), "f"(r5), "f"(r6), "f"(r7)
        : "memory");
}

extern "C" void kernel_launch(void* const* d_in, const int* in_sizes, int n_in,
                              void* d_out, int out_size)
{
    const float* x  = (const float*)d_in[0];
    const int*   ip = (const int*)d_in[1];
    float* out = (float*)d_out;

    const long total8 = (long)out_size / 8;   // 3,145,728
    const int threads = 256;
    const int blocks = (int)((total8 + threads - 1) / threads);  // 12288
    slice_stride2_kernel<<<blocks, threads>>>(x, ip, out, total8);
}